// round 1
// baseline (speedup 1.0000x reference)
#include <cuda_runtime.h>

// ---------------- static scratch (no allocations allowed) ----------------
// x buffer: holds transposed fe [B,F,32] for stage 1, then activations [B,F,64]
// y buffer: raw conv output [B,F,64]
#define MAXE (4 * 50000 * 64)
static __device__ __align__(16) float g_xbuf[MAXE];
static __device__ __align__(16) float g_ybuf[MAXE];
// per-block BN partial sums: up to 3200 blocks * 64 channels
static __device__ __align__(16) float g_psum[3200 * 64];
static __device__ __align__(16) float g_psumsq[3200 * 64];
// folded BN coefficients per stage: y_norm = a*y + s
static __device__ __align__(16) float g_coefA[3 * 64];
static __device__ __align__(16) float g_coefS[3 * 64];

__device__ __forceinline__ float lrelu(float v) { return v >= 0.f ? v : 0.2f * v; }

// ---------------- transpose fe [B,C,F] -> g_xbuf [B,F,C] ----------------
__global__ void k_transpose(const float* __restrict__ fe, int C, int F) {
    __shared__ float sm[32][33];
    int b = blockIdx.z;
    int f0 = blockIdx.x * 32;
    int tx = threadIdx.x, ty = threadIdx.y;
#pragma unroll
    for (int r = 0; r < 4; r++) {
        int c = ty + r * 8;
        int f = f0 + tx;
        float v = 0.f;
        if (f < F && c < C) v = fe[((size_t)b * C + c) * F + f];
        sm[c][tx] = v;
    }
    __syncthreads();
#pragma unroll
    for (int r = 0; r < 4; r++) {
        int f = f0 + ty + r * 8;
        int c = tx;
        if (f < F && c < C) g_xbuf[((size_t)b * F + f) * C + c] = sm[c][ty + r * 8];
    }
}

// ---------------- fused gather + feature build + 64x64 GEMM ----------------
// Input activations read from g_xbuf [B,F,CIN]; output raw conv written to
// g_ybuf [B,F,64]; deterministic per-block channel sums to g_psum/g_psumsq.
template <int CIN>
__global__ __launch_bounds__(256) void k_conv(const int* __restrict__ gidx,
                                              const float* __restrict__ w,
                                              const float* __restrict__ bias,
                                              int F) {
    constexpr int K = 4 * CIN;  // contraction length (C * 4 features)
    extern __shared__ float sm[];
    float* Wsm = sm;              // [K][64]  A matrix: Wsm[kk*64+o]
    float* G = Wsm + K * 64;      // [K][64]  B matrix: G[kk*64+fi]
    float* redS = G + K * 64;     // [64][16]
    float* redQ = redS + 64 * 16; // [64][16]
    int* sidx = (int*)(redQ + 64 * 16);  // [64][3]

    int t = threadIdx.x;
    int b = blockIdx.y;
    int f0 = blockIdx.x * 64;
    int nv = F - f0; if (nv > 64) nv = 64;

    // stage weights into smem: w layout [O][CIN][4] == [O][K] row-major
    for (int i = t; i < K * 64; i += 256) {
        int kk = i >> 6, o = i & 63;
        Wsm[i] = __ldg(&w[o * K + kk]);
    }
    // neighbor indices for this face tile
    if (t < 192) {
        int fi = t / 3, j = t - fi * 3;
        int f = f0 + fi;
        sidx[t] = (f < F) ? __ldg(&gidx[((size_t)b * F + f) * 3 + j]) : 0;
    }
    __syncthreads();

    // gather + symmetric feature build: thread t -> (cq = t>>6 channel quarter,
    // fi = t&63 face).  Contiguous fi within a warp => conflict-free STS.
    {
        int cq = t >> 6;
        int fi = t & 63;
        if (fi < nv) {
            int fc = f0 + fi;
            size_t base_c = ((size_t)b * F + fc) * CIN + cq * (CIN / 4);
            size_t base_1 = ((size_t)b * F + sidx[fi * 3 + 0]) * CIN + cq * (CIN / 4);
            size_t base_2 = ((size_t)b * F + sidx[fi * 3 + 1]) * CIN + cq * (CIN / 4);
            size_t base_3 = ((size_t)b * F + sidx[fi * 3 + 2]) * CIN + cq * (CIN / 4);
#pragma unroll
            for (int i = 0; i < CIN / 16; i++) {
                float4 xc = *(const float4*)&g_xbuf[base_c + i * 4];
                float4 a1 = *(const float4*)&g_xbuf[base_1 + i * 4];
                float4 a2 = *(const float4*)&g_xbuf[base_2 + i * 4];
                float4 a3 = *(const float4*)&g_xbuf[base_3 + i * 4];
                int c0 = cq * (CIN / 4) + i * 4;
                float xs[4] = {xc.x, xc.y, xc.z, xc.w};
                float n1[4] = {a1.x, a1.y, a1.z, a1.w};
                float n2[4] = {a2.x, a2.y, a2.z, a2.w};
                float n3[4] = {a3.x, a3.y, a3.z, a3.w};
#pragma unroll
                for (int cc = 0; cc < 4; cc++) {
                    int base = (c0 + cc) * 256 + fi;  // (c*4+k)*64, k in 0..3
                    float s = n1[cc] + n2[cc] + n3[cc];
                    float d = fabsf(n1[cc] - n2[cc]) + fabsf(n2[cc] - n3[cc]) +
                              fabsf(n3[cc] - n1[cc]);
                    float m = fmaxf(n1[cc], fmaxf(n2[cc], n3[cc]));
                    G[base] = xs[cc];
                    G[base + 64] = s;
                    G[base + 128] = d;
                    G[base + 192] = m;
                }
            }
        } else {
#pragma unroll
            for (int i = 0; i < CIN / 16; i++) {
                int c0 = cq * (CIN / 4) + i * 4;
#pragma unroll
                for (int cc = 0; cc < 4; cc++) {
                    int base = (c0 + cc) * 256 + fi;
                    G[base] = 0.f; G[base + 64] = 0.f;
                    G[base + 128] = 0.f; G[base + 192] = 0.f;
                }
            }
        }
    }
    __syncthreads();

    // register-blocked GEMM: 16x16 threads, 4x4 microtile, M=64 (out ch), N=64 faces
    int ty = t >> 4, tx = t & 15;
    float acc[4][4];
#pragma unroll
    for (int i = 0; i < 4; i++)
#pragma unroll
        for (int j = 0; j < 4; j++) acc[i][j] = 0.f;

#pragma unroll 8
    for (int kk = 0; kk < K; kk++) {
        float4 av = *(const float4*)&Wsm[kk * 64 + ty * 4];
        float4 bv = *(const float4*)&G[kk * 64 + tx * 4];
        acc[0][0] += av.x * bv.x; acc[0][1] += av.x * bv.y;
        acc[0][2] += av.x * bv.z; acc[0][3] += av.x * bv.w;
        acc[1][0] += av.y * bv.x; acc[1][1] += av.y * bv.y;
        acc[1][2] += av.y * bv.z; acc[1][3] += av.y * bv.w;
        acc[2][0] += av.z * bv.x; acc[2][1] += av.z * bv.y;
        acc[2][2] += av.z * bv.z; acc[2][3] += av.z * bv.w;
        acc[3][0] += av.w * bv.x; acc[3][1] += av.w * bv.y;
        acc[3][2] += av.w * bv.z; acc[3][3] += av.w * bv.w;
    }

    // epilogue: bias, store y [B,F,64], deterministic channel sum/sumsq
    float4 b4 = *(const float4*)&bias[ty * 4];
    float ls[4] = {0.f, 0.f, 0.f, 0.f};
    float lq[4] = {0.f, 0.f, 0.f, 0.f};
#pragma unroll
    for (int j = 0; j < 4; j++) {
        int fi = tx * 4 + j;
        if (fi < nv) {
            float4 v;
            v.x = acc[0][j] + b4.x;
            v.y = acc[1][j] + b4.y;
            v.z = acc[2][j] + b4.z;
            v.w = acc[3][j] + b4.w;
            *(float4*)&g_ybuf[((size_t)b * F + f0 + fi) * 64 + ty * 4] = v;
            ls[0] += v.x; lq[0] += v.x * v.x;
            ls[1] += v.y; lq[1] += v.y * v.y;
            ls[2] += v.z; lq[2] += v.z * v.z;
            ls[3] += v.w; lq[3] += v.w * v.w;
        }
    }
#pragma unroll
    for (int i = 0; i < 4; i++) {
        redS[(ty * 4 + i) * 16 + tx] = ls[i];
        redQ[(ty * 4 + i) * 16 + tx] = lq[i];
    }
    __syncthreads();
    if (t < 64) {
        float s = 0.f, q = 0.f;
#pragma unroll
        for (int j = 0; j < 16; j++) { s += redS[t * 16 + j]; q += redQ[t * 16 + j]; }
        int bid = blockIdx.y * gridDim.x + blockIdx.x;
        g_psum[bid * 64 + t] = s;
        g_psumsq[bid * 64 + t] = q;
    }
}

// ---------------- BN stats finalize: fold into a*y + s ----------------
__global__ void k_stats(const float* __restrict__ gamma,
                        const float* __restrict__ beta, int stage, int nblk,
                        float invN) {
    __shared__ float smS[4][64], smQ[4][64];
    int t = threadIdx.x;       // 256
    int c = t & 63, sl = t >> 6;
    float s = 0.f, q = 0.f;
    for (int i = sl; i < nblk; i += 4) {
        s += g_psum[i * 64 + c];
        q += g_psumsq[i * 64 + c];
    }
    smS[sl][c] = s; smQ[sl][c] = q;
    __syncthreads();
    if (t < 64) {
        float ss = smS[0][t] + smS[1][t] + smS[2][t] + smS[3][t];
        float qq = smQ[0][t] + smQ[1][t] + smQ[2][t] + smQ[3][t];
        float m = ss * invN;
        float var = qq * invN - m * m;
        float rstd = rsqrtf(var + 1e-5f);
        float a = gamma[t] * rstd;
        g_coefA[stage * 64 + t] = a;
        g_coefS[stage * 64 + t] = beta[t] - m * a;
    }
}

// ---------------- apply BN + (residual) + lrelu -> g_xbuf [B,F,64] ----------------
__global__ void k_apply(int stage, int res, int nvec) {
    int i = blockIdx.x * blockDim.x + threadIdx.x;
    if (i >= nvec) return;
    int c4 = i & 15;  // float4 index within 64-channel face
    float4 a = *(const float4*)&g_coefA[stage * 64 + c4 * 4];
    float4 s = *(const float4*)&g_coefS[stage * 64 + c4 * 4];
    float4 yv = ((const float4*)g_ybuf)[i];
    float4 o;
    o.x = a.x * yv.x + s.x;
    o.y = a.y * yv.y + s.y;
    o.z = a.z * yv.z + s.z;
    o.w = a.w * yv.w + s.w;
    if (res) {
        float4 xv = ((const float4*)g_xbuf)[i];
        o.x += xv.x; o.y += xv.y; o.z += xv.z; o.w += xv.w;
    }
    o.x = lrelu(o.x); o.y = lrelu(o.y); o.z = lrelu(o.z); o.w = lrelu(o.w);
    ((float4*)g_xbuf)[i] = o;
}

// ---------------- final: BN + residual + lrelu + transpose to [B,O,F] ----------------
__global__ void k_apply_out(float* __restrict__ out, int F) {
    __shared__ float sm[32][33];
    int b = blockIdx.z;
    int o0 = blockIdx.y * 32;
    int f0 = blockIdx.x * 32;
    int tx = threadIdx.x, ty = threadIdx.y;
#pragma unroll
    for (int r = 0; r < 4; r++) {
        int f = f0 + ty + r * 8;
        int o = o0 + tx;
        float v = 0.f;
        if (f < F) {
            float a = g_coefA[2 * 64 + o], s = g_coefS[2 * 64 + o];
            size_t idx = ((size_t)b * F + f) * 64 + o;
            v = lrelu(a * g_ybuf[idx] + s + g_xbuf[idx]);
        }
        sm[ty + r * 8][tx] = v;
    }
    __syncthreads();
#pragma unroll
    for (int r = 0; r < 4; r++) {
        int o = o0 + ty + r * 8;
        int f = f0 + tx;
        if (f < F) out[((size_t)b * 64 + o) * F + f] = sm[tx][ty + r * 8];
    }
}

// ---------------- host launcher ----------------
extern "C" void kernel_launch(void* const* d_in, const int* in_sizes, int n_in,
                              void* d_out, int out_size) {
    const float* fe  = (const float*)d_in[0];
    const int*   gm  = (const int*)d_in[1];
    const float* w1  = (const float*)d_in[2];
    const float* b1  = (const float*)d_in[3];
    const float* w2a = (const float*)d_in[4];
    const float* b2a = (const float*)d_in[5];
    const float* w2b = (const float*)d_in[6];
    const float* b2b = (const float*)d_in[7];
    const float* g0  = (const float*)d_in[8];
    const float* be0 = (const float*)d_in[9];
    const float* g1  = (const float*)d_in[10];
    const float* be1 = (const float*)d_in[11];
    const float* g2  = (const float*)d_in[12];
    const float* be2 = (const float*)d_in[13];

    const int B = 4;
    const int F = in_sizes[1] / (3 * B);          // 50000
    const int Cin = in_sizes[0] / (B * F);        // 32

    // dynamic smem sizes: W + G + red arrays + indices
    const size_t sh1 = (size_t)(2 * (4 * 32) * 64 + 2 * 64 * 16) * 4 + 192 * 4;
    const size_t sh2 = (size_t)(2 * (4 * 64) * 64 + 2 * 64 * 16) * 4 + 192 * 4;
    cudaFuncSetAttribute(k_conv<32>, cudaFuncAttributeMaxDynamicSharedMemorySize, (int)sh1);
    cudaFuncSetAttribute(k_conv<64>, cudaFuncAttributeMaxDynamicSharedMemorySize, (int)sh2);

    dim3 tb(32, 8);
    int ftiles32 = (F + 31) / 32;
    int fb = (F + 63) / 64;
    int nblk = fb * B;
    float invN = 1.0f / (float)(B * F);
    int nvec = B * F * 16;  // float4 count over [B,F,64]

    // stage 0: transpose fe, conv1, stats, apply (no residual)
    k_transpose<<<dim3(ftiles32, 1, B), tb>>>(fe, Cin, F);
    k_conv<32><<<dim3(fb, B), 256, sh1>>>(gm, w1, b1, F);
    k_stats<<<1, 256>>>(g0, be0, 0, nblk, invN);
    k_apply<<<(nvec + 255) / 256, 256>>>(0, 0, nvec);

    // stage 1: conv2a, stats, apply with residual (in-place x)
    k_conv<64><<<dim3(fb, B), 256, sh2>>>(gm, w2a, b2a, F);
    k_stats<<<1, 256>>>(g1, be1, 1, nblk, invN);
    k_apply<<<(nvec + 255) / 256, 256>>>(1, 1, nvec);

    // stage 2: conv2b, stats, fused final apply+transpose to d_out [B,O,F]
    k_conv<64><<<dim3(fb, B), 256, sh2>>>(gm, w2b, b2b, F);
    k_stats<<<1, 256>>>(g2, be2, 2, nblk, invN);
    k_apply_out<<<dim3(ftiles32, 2, B), tb>>>((float*)d_out, F);
}

// round 2
// speedup vs baseline: 1.2495x; 1.2495x over previous
#include <cuda_runtime.h>

// ---------------- static scratch (no allocations allowed) ----------------
#define MAXE (4 * 50000 * 64)
static __device__ __align__(16) float g_xbuf[MAXE];   // activations [B,F,C]
static __device__ __align__(16) float g_ybuf[MAXE];   // raw conv out [B,F,64]
static __device__ __align__(16) float g_psum[3200 * 64];
static __device__ __align__(16) float g_psumsq[3200 * 64];
static __device__ __align__(16) float g_coefA[3 * 64];
static __device__ __align__(16) float g_coefS[3 * 64];

__device__ __forceinline__ float lrelu(float v) { return v >= 0.f ? v : 0.2f * v; }

// packed dual-fp32 FMA (sm_100+): d = a*b + d elementwise on float2
__device__ __forceinline__ void fma2(float2& d, const float2& a, const float2& b) {
    asm("fma.rn.f32x2 %0, %1, %2, %0;"
        : "+l"(*reinterpret_cast<unsigned long long*>(&d))
        : "l"(*reinterpret_cast<const unsigned long long*>(&a)),
          "l"(*reinterpret_cast<const unsigned long long*>(&b)));
}
__device__ __forceinline__ float2 dup2(float v) { float2 r; r.x = v; r.y = v; return r; }

// ---------------- transpose fe [B,C,F] -> g_xbuf [B,F,C] ----------------
__global__ void k_transpose(const float* __restrict__ fe, int C, int F) {
    __shared__ float sm[32][33];
    int b = blockIdx.z;
    int f0 = blockIdx.x * 32;
    int tx = threadIdx.x, ty = threadIdx.y;
#pragma unroll
    for (int r = 0; r < 4; r++) {
        int c = ty + r * 8;
        int f = f0 + tx;
        float v = 0.f;
        if (f < F && c < C) v = fe[((size_t)b * C + c) * F + f];
        sm[c][tx] = v;
    }
    __syncthreads();
#pragma unroll
    for (int r = 0; r < 4; r++) {
        int f = f0 + ty + r * 8;
        int c = tx;
        if (f < F && c < C) g_xbuf[((size_t)b * F + f) * C + c] = sm[c][ty + r * 8];
    }
}

// ---------------- fused gather + feature build + GEMM (128-face tile) ----------------
// K = 4*CIN contraction. Double-buffered 32-row G chunks (8 channels each),
// register-prefetched gathers, 4(O)x8(F) microtile with packed f32x2 FMA.
template <int CIN>
__global__ __launch_bounds__(256, 2) void k_conv(const int* __restrict__ gidx,
                                                 const float* __restrict__ w,
                                                 const float* __restrict__ bias,
                                                 int F) {
    constexpr int K = 4 * CIN;
    constexpr int NG = CIN / 8;          // number of 8-channel chunks
    extern __shared__ float sm[];
    float* Wsm = sm;                     // [K][64]
    float* Gb = Wsm + K * 64;            // 2 x [32][128]
    float* redS = Gb + 2 * 32 * 128;     // [64][16]
    float* redQ = redS + 64 * 16;        // [64][16]
    int* sidx = (int*)(redQ + 64 * 16);  // [128][3]

    int t = threadIdx.x;
    int b = blockIdx.y;
    int f0 = blockIdx.x * 128;
    int nv = F - f0; if (nv > 128) nv = 128;

    // stage weights: w [O][CIN][4] == [O][K]; Wsm[kk*64+o]
    for (int i = t; i < K * 64; i += 256) {
        int kk = i >> 6, o = i & 63;
        Wsm[i] = __ldg(&w[o * K + kk]);
    }
    // neighbor indices for this tile
    for (int i = t; i < 128 * 3; i += 256) {
        int fi = i / 3, j = i - fi * 3;
        sidx[i] = (f0 + fi < F) ? __ldg(&gidx[((size_t)b * F + f0 + fi) * 3 + j]) : 0;
    }
    __syncthreads();

    // gather roles: fi = t&127, half = t>>7 selects 4 channels within 8-ch chunk
    int fi = t & 127, half = t >> 7;
    bool valid = fi < nv;
    size_t bc = 0, bn1 = 0, bn2 = 0, bn3 = 0;
    if (valid) {
        bc  = ((size_t)b * F + f0 + fi) * CIN + half * 4;
        bn1 = ((size_t)b * F + sidx[fi * 3 + 0]) * CIN + half * 4;
        bn2 = ((size_t)b * F + sidx[fi * 3 + 1]) * CIN + half * 4;
        bn3 = ((size_t)b * F + sidx[fi * 3 + 2]) * CIN + half * 4;
    }

    float4 rc, r1, r2, r3;
    auto LOADC = [&](int g) {
        if (valid) {
            int off = g * 8;
            rc = *(const float4*)&g_xbuf[bc + off];
            r1 = *(const float4*)&g_xbuf[bn1 + off];
            r2 = *(const float4*)&g_xbuf[bn2 + off];
            r3 = *(const float4*)&g_xbuf[bn3 + off];
        } else {
            rc = make_float4(0.f, 0.f, 0.f, 0.f);
            r1 = rc; r2 = rc; r3 = rc;
        }
    };
    auto STS = [&](float* Gc) {
        const float* pc = (const float*)&rc;
        const float* p1 = (const float*)&r1;
        const float* p2 = (const float*)&r2;
        const float* p3 = (const float*)&r3;
#pragma unroll
        for (int cc = 0; cc < 4; cc++) {
            int r = (half * 4 + cc) * 4;
            float a = p1[cc], b2 = p2[cc], c3 = p3[cc];
            float s = a + b2 + c3;
            float d = fabsf(a - b2) + fabsf(b2 - c3) + fabsf(c3 - a);
            float m = fmaxf(a, fmaxf(b2, c3));
            Gc[(r + 0) * 128 + fi] = pc[cc];
            Gc[(r + 1) * 128 + fi] = s;
            Gc[(r + 2) * 128 + fi] = d;
            Gc[(r + 3) * 128 + fi] = m;
        }
    };

    // GEMM roles: ty = O quarter, tx = face octet
    int ty = t >> 4, tx = t & 15;
    float2 acc[4][4];
#pragma unroll
    for (int i = 0; i < 4; i++)
#pragma unroll
        for (int j = 0; j < 4; j++) acc[i][j] = make_float2(0.f, 0.f);

    auto GEMM = [&](const float* Gc, int g) {
#pragma unroll 4
        for (int kk = 0; kk < 32; kk++) {
            float4 av = *(const float4*)&Wsm[(g * 32 + kk) * 64 + ty * 4];
            float4 q0 = *(const float4*)&Gc[kk * 128 + tx * 8];
            float4 q1 = *(const float4*)&Gc[kk * 128 + tx * 8 + 4];
            float2 bp0 = make_float2(q0.x, q0.y);
            float2 bp1 = make_float2(q0.z, q0.w);
            float2 bp2 = make_float2(q1.x, q1.y);
            float2 bp3 = make_float2(q1.z, q1.w);
            float2 a0 = dup2(av.x), a1 = dup2(av.y), a2 = dup2(av.z), a3 = dup2(av.w);
            fma2(acc[0][0], a0, bp0); fma2(acc[0][1], a0, bp1);
            fma2(acc[0][2], a0, bp2); fma2(acc[0][3], a0, bp3);
            fma2(acc[1][0], a1, bp0); fma2(acc[1][1], a1, bp1);
            fma2(acc[1][2], a1, bp2); fma2(acc[1][3], a1, bp3);
            fma2(acc[2][0], a2, bp0); fma2(acc[2][1], a2, bp1);
            fma2(acc[2][2], a2, bp2); fma2(acc[2][3], a2, bp3);
            fma2(acc[3][0], a3, bp0); fma2(acc[3][1], a3, bp1);
            fma2(acc[3][2], a3, bp2); fma2(acc[3][3], a3, bp3);
        }
    };

    // software pipeline: prefetch next chunk's gathers behind current GEMM
    LOADC(0);
    STS(Gb);
    __syncthreads();
#pragma unroll 1
    for (int g = 0; g < NG; g++) {
        if (g + 1 < NG) LOADC(g + 1);
        GEMM(Gb + (g & 1) * 4096, g);
        if (g + 1 < NG) STS(Gb + ((g + 1) & 1) * 4096);
        __syncthreads();
    }

    // epilogue: bias, store y [B,F,64], deterministic channel sum/sumsq
    float4 b4 = *(const float4*)&bias[ty * 4];
    float ls[4] = {0.f, 0.f, 0.f, 0.f};
    float lq[4] = {0.f, 0.f, 0.f, 0.f};
#pragma unroll
    for (int j2 = 0; j2 < 4; j2++) {
        int fb0 = tx * 8 + j2 * 2;
        if (fb0 < nv) {
            float4 v;
            v.x = acc[0][j2].x + b4.x;
            v.y = acc[1][j2].x + b4.y;
            v.z = acc[2][j2].x + b4.z;
            v.w = acc[3][j2].x + b4.w;
            *(float4*)&g_ybuf[((size_t)b * F + f0 + fb0) * 64 + ty * 4] = v;
            ls[0] += v.x; lq[0] += v.x * v.x;
            ls[1] += v.y; lq[1] += v.y * v.y;
            ls[2] += v.z; lq[2] += v.z * v.z;
            ls[3] += v.w; lq[3] += v.w * v.w;
        }
        if (fb0 + 1 < nv) {
            float4 v;
            v.x = acc[0][j2].y + b4.x;
            v.y = acc[1][j2].y + b4.y;
            v.z = acc[2][j2].y + b4.z;
            v.w = acc[3][j2].y + b4.w;
            *(float4*)&g_ybuf[((size_t)b * F + f0 + fb0 + 1) * 64 + ty * 4] = v;
            ls[0] += v.x; lq[0] += v.x * v.x;
            ls[1] += v.y; lq[1] += v.y * v.y;
            ls[2] += v.z; lq[2] += v.z * v.z;
            ls[3] += v.w; lq[3] += v.w * v.w;
        }
    }
#pragma unroll
    for (int i = 0; i < 4; i++) {
        redS[(ty * 4 + i) * 16 + tx] = ls[i];
        redQ[(ty * 4 + i) * 16 + tx] = lq[i];
    }
    __syncthreads();
    if (t < 64) {
        float s = 0.f, q = 0.f;
#pragma unroll
        for (int j = 0; j < 16; j++) { s += redS[t * 16 + j]; q += redQ[t * 16 + j]; }
        int bid = blockIdx.y * gridDim.x + blockIdx.x;
        g_psum[bid * 64 + t] = s;
        g_psumsq[bid * 64 + t] = q;
    }
}

// ---------------- BN stats finalize: fold into a*y + s ----------------
__global__ void k_stats(const float* __restrict__ gamma,
                        const float* __restrict__ beta, int stage, int nblk,
                        float invN) {
    __shared__ float smS[4][64], smQ[4][64];
    int t = threadIdx.x;  // 256
    int c = t & 63, sl = t >> 6;
    float s = 0.f, q = 0.f;
    for (int i = sl; i < nblk; i += 4) {
        s += g_psum[i * 64 + c];
        q += g_psumsq[i * 64 + c];
    }
    smS[sl][c] = s; smQ[sl][c] = q;
    __syncthreads();
    if (t < 64) {
        float ss = smS[0][t] + smS[1][t] + smS[2][t] + smS[3][t];
        float qq = smQ[0][t] + smQ[1][t] + smQ[2][t] + smQ[3][t];
        float m = ss * invN;
        float var = qq * invN - m * m;
        float rstd = rsqrtf(var + 1e-5f);
        float a = gamma[t] * rstd;
        g_coefA[stage * 64 + t] = a;
        g_coefS[stage * 64 + t] = beta[t] - m * a;
    }
}

// ---------------- apply BN + (residual) + lrelu -> g_xbuf [B,F,64] ----------------
__global__ void k_apply(int stage, int res, int nvec) {
    int i = blockIdx.x * blockDim.x + threadIdx.x;
    if (i >= nvec) return;
    int c4 = i & 15;
    float4 a = *(const float4*)&g_coefA[stage * 64 + c4 * 4];
    float4 s = *(const float4*)&g_coefS[stage * 64 + c4 * 4];
    float4 yv = ((const float4*)g_ybuf)[i];
    float4 o;
    o.x = a.x * yv.x + s.x;
    o.y = a.y * yv.y + s.y;
    o.z = a.z * yv.z + s.z;
    o.w = a.w * yv.w + s.w;
    if (res) {
        float4 xv = ((const float4*)g_xbuf)[i];
        o.x += xv.x; o.y += xv.y; o.z += xv.z; o.w += xv.w;
    }
    o.x = lrelu(o.x); o.y = lrelu(o.y); o.z = lrelu(o.z); o.w = lrelu(o.w);
    ((float4*)g_xbuf)[i] = o;
}

// ---------------- final: BN + residual + lrelu + transpose to [B,O,F] ----------------
__global__ void k_apply_out(float* __restrict__ out, int F) {
    __shared__ float sm[32][33];
    int b = blockIdx.z;
    int o0 = blockIdx.y * 32;
    int f0 = blockIdx.x * 32;
    int tx = threadIdx.x, ty = threadIdx.y;
#pragma unroll
    for (int r = 0; r < 4; r++) {
        int f = f0 + ty + r * 8;
        int o = o0 + tx;
        float v = 0.f;
        if (f < F) {
            float a = g_coefA[2 * 64 + o], s = g_coefS[2 * 64 + o];
            size_t idx = ((size_t)b * F + f) * 64 + o;
            v = lrelu(a * g_ybuf[idx] + s + g_xbuf[idx]);
        }
        sm[ty + r * 8][tx] = v;
    }
    __syncthreads();
#pragma unroll
    for (int r = 0; r < 4; r++) {
        int o = o0 + ty + r * 8;
        int f = f0 + tx;
        if (f < F) out[((size_t)b * 64 + o) * F + f] = sm[tx][ty + r * 8];
    }
}

// ---------------- host launcher ----------------
extern "C" void kernel_launch(void* const* d_in, const int* in_sizes, int n_in,
                              void* d_out, int out_size) {
    const float* fe  = (const float*)d_in[0];
    const int*   gm  = (const int*)d_in[1];
    const float* w1  = (const float*)d_in[2];
    const float* b1  = (const float*)d_in[3];
    const float* w2a = (const float*)d_in[4];
    const float* b2a = (const float*)d_in[5];
    const float* w2b = (const float*)d_in[6];
    const float* b2b = (const float*)d_in[7];
    const float* g0  = (const float*)d_in[8];
    const float* be0 = (const float*)d_in[9];
    const float* g1  = (const float*)d_in[10];
    const float* be1 = (const float*)d_in[11];
    const float* g2  = (const float*)d_in[12];
    const float* be2 = (const float*)d_in[13];

    const int B = 4;
    const int F = in_sizes[1] / (3 * B);      // 50000
    const int Cin = in_sizes[0] / (B * F);    // 32

    // smem: W[K][64] + 2x[32][128] G + 2x[64][16] red + [128][3] idx
    const size_t sh1 = (size_t)(4 * 32 * 64 + 2 * 32 * 128 + 2 * 64 * 16) * 4 + 128 * 3 * 4;
    const size_t sh2 = (size_t)(4 * 64 * 64 + 2 * 32 * 128 + 2 * 64 * 16) * 4 + 128 * 3 * 4;
    cudaFuncSetAttribute(k_conv<32>, cudaFuncAttributeMaxDynamicSharedMemorySize, (int)sh1);
    cudaFuncSetAttribute(k_conv<64>, cudaFuncAttributeMaxDynamicSharedMemorySize, (int)sh2);

    dim3 tb(32, 8);
    int ftiles32 = (F + 31) / 32;
    int fb = (F + 127) / 128;
    int nblk = fb * B;
    float invN = 1.0f / (float)(B * F);
    int nvec = B * F * 16;  // float4 count over [B,F,64]

    // stage 0
    k_transpose<<<dim3(ftiles32, 1, B), tb>>>(fe, Cin, F);
    k_conv<32><<<dim3(fb, B), 256, sh1>>>(gm, w1, b1, F);
    k_stats<<<1, 256>>>(g0, be0, 0, nblk, invN);
    k_apply<<<(nvec + 255) / 256, 256>>>(0, 0, nvec);

    // stage 1 (residual)
    k_conv<64><<<dim3(fb, B), 256, sh2>>>(gm, w2a, b2a, F);
    k_stats<<<1, 256>>>(g1, be1, 1, nblk, invN);
    k_apply<<<(nvec + 255) / 256, 256>>>(1, 1, nvec);

    // stage 2 (residual, fused final transpose)
    k_conv<64><<<dim3(fb, B), 256, sh2>>>(gm, w2b, b2b, F);
    k_stats<<<1, 256>>>(g2, be2, 2, nblk, invN);
    k_apply_out<<<dim3(ftiles32, 2, B), tb>>>((float*)d_out, F);
}

// round 5
// speedup vs baseline: 2.2444x; 1.7963x over previous
#include <cuda_runtime.h>
#include <cstdint>

// ---------------- static scratch ----------------
#define MAXE (4 * 50000 * 64)
static __device__ __align__(16) float g_xbuf[MAXE];   // activations [B,F,C]
static __device__ __align__(16) float g_ybuf[MAXE];   // raw conv out [B,F,64]
static __device__ __align__(16) float g_wT[3][256 * 64];  // transposed weights [K][64]
static __device__ __align__(16) float g_psum[3200 * 64];
static __device__ __align__(16) float g_psumsq[3200 * 64];
static __device__ __align__(16) float g_coefA[3 * 64];
static __device__ __align__(16) float g_coefS[3 * 64];

__device__ __forceinline__ float lrelu(float v) { return v >= 0.f ? v : 0.2f * v; }

__device__ __forceinline__ void fma2(float2& d, const float2& a, const float2& b) {
    asm("fma.rn.f32x2 %0, %1, %2, %0;"
        : "+l"(*reinterpret_cast<unsigned long long*>(&d))
        : "l"(*reinterpret_cast<const unsigned long long*>(&a)),
          "l"(*reinterpret_cast<const unsigned long long*>(&b)));
}
__device__ __forceinline__ float2 dup2(float v) { float2 r; r.x = v; r.y = v; return r; }

__device__ __forceinline__ uint32_t s2u(const void* p) {
    uint32_t a;
    asm("{ .reg .u64 t; cvta.to.shared.u64 t, %1; cvt.u32.u64 %0, t; }" : "=r"(a) : "l"(p));
    return a;
}
__device__ __forceinline__ void cpa16(uint32_t dst, const void* src) {
    asm volatile("cp.async.cg.shared.global [%0], [%1], 16;" :: "r"(dst), "l"(src));
}
#define CPA_COMMIT() asm volatile("cp.async.commit_group;" ::: "memory")
#define CPA_WAIT0()  asm volatile("cp.async.wait_group 0;" ::: "memory")

// ---------------- weight transpose prep: w [64][K] -> g_wT[sel] [K][64] ----------------
__global__ void k_wprep(const float* __restrict__ w, int sel, int K) {
    int i = blockIdx.x * 256 + threadIdx.x;
    if (i < K * 64) {
        int k = i >> 6, o = i & 63;
        g_wT[sel][i] = w[o * K + k];
    }
}

// ---------------- transpose fe [B,C,F] -> g_xbuf [B,F,C] ----------------
__global__ void k_transpose(const float* __restrict__ fe, int C, int F) {
    __shared__ float sm[32][33];
    int b = blockIdx.z;
    int f0 = blockIdx.x * 32;
    int tx = threadIdx.x, ty = threadIdx.y;
#pragma unroll
    for (int r = 0; r < 4; r++) {
        int c = ty + r * 8;
        int f = f0 + tx;
        float v = 0.f;
        if (f < F && c < C) v = fe[((size_t)b * C + c) * F + f];
        sm[c][tx] = v;
    }
    __syncthreads();
#pragma unroll
    for (int r = 0; r < 4; r++) {
        int f = f0 + ty + r * 8;
        int c = tx;
        if (f < F && c < C) g_xbuf[((size_t)b * F + f) * C + c] = sm[c][ty + r * 8];
    }
}

// ---------------- fused gather + feature build + balanced GEMM ----------------
// Tile: 128 faces x 64 out. 128 threads, 8x8 microtile (f32x2 over face pairs).
// K = 4*CIN processed in 32-row chunks (8 input channels each).
// cp.async gathers raw neighbor data into smem; features built per-thread;
// weights streamed from pre-transposed g_wT via cp.async (double-buffered).
template <int CIN>
__global__ __launch_bounds__(128, 3) void k_conv(const int* __restrict__ gidx,
                                                 int wsel,
                                                 const float* __restrict__ bias,
                                                 int F) {
    constexpr int NG = CIN / 8;               // number of 32-row K chunks
    // smem layout (bytes)
    constexpr int OFF_W = 0;                  // 2 x [32][64] f32 = 16384
    constexpr int OFF_G = 16384;              // 2 x [32][128] f32 = 32768
    constexpr int OFF_RAW = 49152;            // [8 planes][128 faces][16B] = 16384
    constexpr int OFF_SIDX = 65536;           // [128][3] int = 1536

    extern __shared__ char smc[];
    uint32_t sb = s2u(smc);
    int* sidx = (int*)(smc + OFF_SIDX);

    int t = threadIdx.x;
    int b = blockIdx.y;
    int f0 = blockIdx.x * 128;
    int nv = F - f0; if (nv > 128) nv = 128;

    // neighbor indices
    for (int i = t; i < 128 * 3; i += 128) {
        int fi = i / 3, j = i - fi * 3;
        sidx[i] = (f0 + fi < F) ? __ldg(&gidx[((size_t)b * F + f0 + fi) * 3 + j]) : 0;
    }
    __syncthreads();

    // per-thread gather sources (thread t owns face t of the tile)
    int fc = f0 + (t < nv ? t : (nv - 1));
    const float* s0 = &g_xbuf[((size_t)b * F + fc) * CIN];
    const float* s1 = &g_xbuf[((size_t)b * F + sidx[t * 3 + 0]) * CIN];
    const float* s2 = &g_xbuf[((size_t)b * F + sidx[t * 3 + 1]) * CIN];
    const float* s3 = &g_xbuf[((size_t)b * F + sidx[t * 3 + 2]) * CIN];
    const float* wT = g_wT[wsel];

    auto ISSUE = [&](int g) {
        // gather: 8 planes x 16B per face (center + 3 neighbors, 8 channels)
        uint32_t rb = sb + OFF_RAW + t * 16;
        const float* ss[4] = {s0, s1, s2, s3};
#pragma unroll
        for (int n = 0; n < 4; n++) {
#pragma unroll
            for (int h = 0; h < 2; h++)
                cpa16(rb + (n * 2 + h) * 2048, ss[n] + g * 8 + h * 4);
        }
        // weights: chunk g rows [g*32 .. g*32+31] x 64, contiguous
        uint32_t wb = sb + OFF_W + (g & 1) * 8192 + t * 64;
        const float* wsrc = wT + g * 2048 + t * 16;
#pragma unroll
        for (int q = 0; q < 4; q++) cpa16(wb + q * 16, wsrc + q * 4);
        CPA_COMMIT();
    };

    auto CONVERT = [&](int g) {
        // read own face's raw data, build 4 symmetric features x 8 channels
        float c[8], n1[8], n2[8], n3[8];
        const float4* rp = (const float4*)(smc + OFF_RAW);
#pragma unroll
        for (int h = 0; h < 2; h++) {
            *(float4*)&c[h * 4]  = rp[(0 * 2 + h) * 128 + t];
            *(float4*)&n1[h * 4] = rp[(1 * 2 + h) * 128 + t];
            *(float4*)&n2[h * 4] = rp[(2 * 2 + h) * 128 + t];
            *(float4*)&n3[h * 4] = rp[(3 * 2 + h) * 128 + t];
        }
        float* Gb = (float*)(smc + OFF_G + (g & 1) * 16384);
        bool fv = t < nv;
#pragma unroll
        for (int cc = 0; cc < 8; cc++) {
            float x1 = n1[cc], x2 = n2[cc], x3 = n3[cc];
            float fcv = fv ? c[cc] : 0.f;
            float fs = fv ? (x1 + x2 + x3) : 0.f;
            float fd = fv ? (fabsf(x1 - x2) + fabsf(x2 - x3) + fabsf(x3 - x1)) : 0.f;
            float fm = fv ? fmaxf(x1, fmaxf(x2, x3)) : 0.f;
            int r = cc * 4;
            Gb[(r + 0) * 128 + t] = fcv;
            Gb[(r + 1) * 128 + t] = fs;
            Gb[(r + 2) * 128 + t] = fd;
            Gb[(r + 3) * 128 + t] = fm;
        }
    };

    // GEMM roles: fy = t>>3 (face octet 0..15), ox = t&7 (out octet)
    int fy = t >> 3, ox = t & 7;
    float2 acc[8][4];
#pragma unroll
    for (int i = 0; i < 8; i++)
#pragma unroll
        for (int j = 0; j < 4; j++) acc[i][j] = make_float2(0.f, 0.f);

    auto GEMM = [&](int g) {
        const float* Wb = (const float*)(smc + OFF_W + (g & 1) * 8192);
        const float* Gb = (const float*)(smc + OFF_G + (g & 1) * 16384);
#pragma unroll 8
        for (int kk = 0; kk < 32; kk++) {
            float4 w0 = *(const float4*)&Wb[kk * 64 + ox * 8];
            float4 w1 = *(const float4*)&Wb[kk * 64 + ox * 8 + 4];
            float4 q0 = *(const float4*)&Gb[kk * 128 + fy * 8];
            float4 q1 = *(const float4*)&Gb[kk * 128 + fy * 8 + 4];
            float2 gp[4];
            gp[0] = make_float2(q0.x, q0.y); gp[1] = make_float2(q0.z, q0.w);
            gp[2] = make_float2(q1.x, q1.y); gp[3] = make_float2(q1.z, q1.w);
            const float* wv = (const float*)&w0;
#pragma unroll
            for (int oi = 0; oi < 4; oi++) {
                float2 wd = dup2(wv[oi]);
                fma2(acc[oi][0], wd, gp[0]); fma2(acc[oi][1], wd, gp[1]);
                fma2(acc[oi][2], wd, gp[2]); fma2(acc[oi][3], wd, gp[3]);
            }
            const float* wv1 = (const float*)&w1;
#pragma unroll
            for (int oi = 0; oi < 4; oi++) {
                float2 wd = dup2(wv1[oi]);
                fma2(acc[4 + oi][0], wd, gp[0]); fma2(acc[4 + oi][1], wd, gp[1]);
                fma2(acc[4 + oi][2], wd, gp[2]); fma2(acc[4 + oi][3], wd, gp[3]);
            }
        }
    };

    // pipeline
    ISSUE(0);
    CPA_WAIT0();
    CONVERT(0);
    __syncthreads();
#pragma unroll 1
    for (int g = 0; g < NG; g++) {
        if (g + 1 < NG) ISSUE(g + 1);   // raw buffer free (consumed pre-sync)
        GEMM(g);
        if (g + 1 < NG) {
            CPA_WAIT0();
            CONVERT(g + 1);
            __syncthreads();
        }
    }
    __syncthreads();

    // epilogue: bias, store y [B,F,64], per-block deterministic sums
    float4 b0 = *(const float4*)&bias[ox * 8];
    float4 b1 = *(const float4*)&bias[ox * 8 + 4];
    const float* bb = (const float*)&b0;
    const float* bb1 = (const float*)&b1;
    float ls[8], lq[8];
#pragma unroll
    for (int i = 0; i < 8; i++) { ls[i] = 0.f; lq[i] = 0.f; }
#pragma unroll
    for (int j = 0; j < 8; j++) {
        int face = fy * 8 + j;
        if (face < nv) {
            float v[8];
#pragma unroll
            for (int oi = 0; oi < 4; oi++) {
                float2 a = acc[oi][j >> 1];
                v[oi] = ((j & 1) ? a.y : a.x) + bb[oi];
            }
#pragma unroll
            for (int oi = 0; oi < 4; oi++) {
                float2 a = acc[4 + oi][j >> 1];
                v[4 + oi] = ((j & 1) ? a.y : a.x) + bb1[oi];
            }
            float* yrow = &g_ybuf[((size_t)b * F + f0 + face) * 64 + ox * 8];
            *(float4*)&yrow[0] = make_float4(v[0], v[1], v[2], v[3]);
            *(float4*)&yrow[4] = make_float4(v[4], v[5], v[6], v[7]);
#pragma unroll
            for (int oi = 0; oi < 8; oi++) { ls[oi] += v[oi]; lq[oi] += v[oi] * v[oi]; }
        }
    }
    // reduce over 16 fy groups (reuse raw area)
    float* redS = (float*)(smc + OFF_RAW);          // [16][64]
    float* redQ = redS + 16 * 64;                   // [16][64]
#pragma unroll
    for (int oi = 0; oi < 8; oi++) {
        redS[fy * 64 + ox * 8 + oi] = ls[oi];
        redQ[fy * 64 + ox * 8 + oi] = lq[oi];
    }
    __syncthreads();
    if (t < 64) {
        float s = 0.f, q = 0.f;
#pragma unroll
        for (int i = 0; i < 16; i++) { s += redS[i * 64 + t]; q += redQ[i * 64 + t]; }
        int bid = blockIdx.y * gridDim.x + blockIdx.x;
        g_psum[bid * 64 + t] = s;
        g_psumsq[bid * 64 + t] = q;
    }
}

// ---------------- BN stats finalize ----------------
__global__ void k_stats(const float* __restrict__ gamma,
                        const float* __restrict__ beta, int stage, int nblk,
                        float invN) {
    __shared__ float smS[4][64], smQ[4][64];
    int t = threadIdx.x;
    int c = t & 63, sl = t >> 6;
    float s = 0.f, q = 0.f;
    for (int i = sl; i < nblk; i += 4) {
        s += g_psum[i * 64 + c];
        q += g_psumsq[i * 64 + c];
    }
    smS[sl][c] = s; smQ[sl][c] = q;
    __syncthreads();
    if (t < 64) {
        float ss = smS[0][t] + smS[1][t] + smS[2][t] + smS[3][t];
        float qq = smQ[0][t] + smQ[1][t] + smQ[2][t] + smQ[3][t];
        float m = ss * invN;
        float var = qq * invN - m * m;
        float rstd = rsqrtf(var + 1e-5f);
        float a = gamma[t] * rstd;
        g_coefA[stage * 64 + t] = a;
        g_coefS[stage * 64 + t] = beta[t] - m * a;
    }
}

// ---------------- apply BN + (residual) + lrelu -> g_xbuf [B,F,64] ----------------
__global__ void k_apply(int stage, int res, int nvec) {
    int i = blockIdx.x * blockDim.x + threadIdx.x;
    if (i >= nvec) return;
    int c4 = i & 15;
    float4 a = *(const float4*)&g_coefA[stage * 64 + c4 * 4];
    float4 s = *(const float4*)&g_coefS[stage * 64 + c4 * 4];
    float4 yv = ((const float4*)g_ybuf)[i];
    float4 o;
    o.x = a.x * yv.x + s.x; o.y = a.y * yv.y + s.y;
    o.z = a.z * yv.z + s.z; o.w = a.w * yv.w + s.w;
    if (res) {
        float4 xv = ((const float4*)g_xbuf)[i];
        o.x += xv.x; o.y += xv.y; o.z += xv.z; o.w += xv.w;
    }
    o.x = lrelu(o.x); o.y = lrelu(o.y); o.z = lrelu(o.z); o.w = lrelu(o.w);
    ((float4*)g_xbuf)[i] = o;
}

// ---------------- final apply + transpose to [B,O,F] ----------------
__global__ void k_apply_out(float* __restrict__ out, int F) {
    __shared__ float sm[32][33];
    int b = blockIdx.z;
    int o0 = blockIdx.y * 32;
    int f0 = blockIdx.x * 32;
    int tx = threadIdx.x, ty = threadIdx.y;
#pragma unroll
    for (int r = 0; r < 4; r++) {
        int f = f0 + ty + r * 8;
        int o = o0 + tx;
        float v = 0.f;
        if (f < F) {
            float a = g_coefA[2 * 64 + o], s = g_coefS[2 * 64 + o];
            size_t idx = ((size_t)b * F + f) * 64 + o;
            v = lrelu(a * g_ybuf[idx] + s + g_xbuf[idx]);
        }
        sm[ty + r * 8][tx] = v;
    }
    __syncthreads();
#pragma unroll
    for (int r = 0; r < 4; r++) {
        int o = o0 + ty + r * 8;
        int f = f0 + tx;
        if (f < F) out[((size_t)b * 64 + o) * F + f] = sm[tx][ty + r * 8];
    }
}

// ---------------- host launcher ----------------
extern "C" void kernel_launch(void* const* d_in, const int* in_sizes, int n_in,
                              void* d_out, int out_size) {
    const float* fe  = (const float*)d_in[0];
    const int*   gm  = (const int*)d_in[1];
    const float* w1  = (const float*)d_in[2];
    const float* b1  = (const float*)d_in[3];
    const float* w2a = (const float*)d_in[4];
    const float* b2a = (const float*)d_in[5];
    const float* w2b = (const float*)d_in[6];
    const float* b2b = (const float*)d_in[7];
    const float* g0  = (const float*)d_in[8];
    const float* be0 = (const float*)d_in[9];
    const float* g1  = (const float*)d_in[10];
    const float* be1 = (const float*)d_in[11];
    const float* g2  = (const float*)d_in[12];
    const float* be2 = (const float*)d_in[13];

    const int B = 4;
    const int F = in_sizes[1] / (3 * B);      // 50000
    const int Cin = in_sizes[0] / (B * F);    // 32

    const int SH = 16384 + 32768 + 16384 + 1536;  // 67072 bytes
    cudaFuncSetAttribute(k_conv<32>, cudaFuncAttributeMaxDynamicSharedMemorySize, SH);
    cudaFuncSetAttribute(k_conv<64>, cudaFuncAttributeMaxDynamicSharedMemorySize, SH);

    dim3 tb(32, 8);
    int ftiles32 = (F + 31) / 32;
    int fb = (F + 127) / 128;
    int nblk = fb * B;
    float invN = 1.0f / (float)(B * F);
    int nvec = B * F * 16;

    // prep: weight transposes + activation transpose
    k_wprep<<<(4 * Cin * 64 + 255) / 256, 256>>>(w1, 0, 4 * Cin);
    k_wprep<<<(256 * 64 + 255) / 256, 256>>>(w2a, 1, 256);
    k_wprep<<<(256 * 64 + 255) / 256, 256>>>(w2b, 2, 256);
    k_transpose<<<dim3(ftiles32, 1, B), tb>>>(fe, Cin, F);

    // stage 0
    k_conv<32><<<dim3(fb, B), 128, SH>>>(gm, 0, b1, F);
    k_stats<<<1, 256>>>(g0, be0, 0, nblk, invN);
    k_apply<<<(nvec + 255) / 256, 256>>>(0, 0, nvec);

    // stage 1 (residual)
    k_conv<64><<<dim3(fb, B), 128, SH>>>(gm, 1, b2a, F);
    k_stats<<<1, 256>>>(g1, be1, 1, nblk, invN);
    k_apply<<<(nvec + 255) / 256, 256>>>(1, 1, nvec);

    // stage 2 (residual, fused final transpose)
    k_conv<64><<<dim3(fb, B), 128, SH>>>(gm, 2, b2b, F);
    k_stats<<<1, 256>>>(g2, be2, 2, nblk, invN);
    k_apply_out<<<dim3(ftiles32, 2, B), tb>>>((float*)d_out, F);
}

// round 6
// speedup vs baseline: 2.4179x; 1.0773x over previous
#include <cuda_runtime.h>
#include <cstdint>

// ---------------- static scratch ----------------
#define MAXE (4 * 50000 * 64)
static __device__ __align__(16) float g_xbuf[MAXE];      // activations [B,F,C]
static __device__ __align__(16) float g_ybuf[MAXE];      // raw conv out [B,F,64]
static __device__ __align__(16) uint32_t g_wThi[3][256 * 64];  // tf32 hi, [K][64]
static __device__ __align__(16) uint32_t g_wTlo[3][256 * 64];  // tf32 lo, [K][64]
static __device__ __align__(16) float g_psum[3200 * 64];
static __device__ __align__(16) float g_psumsq[3200 * 64];
static __device__ __align__(16) float g_coefA[3 * 64];
static __device__ __align__(16) float g_coefS[3 * 64];

__device__ __forceinline__ float lrelu(float v) { return v >= 0.f ? v : 0.2f * v; }

__device__ __forceinline__ uint32_t s2u(const void* p) {
    uint32_t a;
    asm("{ .reg .u64 t; cvta.to.shared.u64 t, %1; cvt.u32.u64 %0, t; }" : "=r"(a) : "l"(p));
    return a;
}
__device__ __forceinline__ void cpa16(uint32_t dst, const void* src) {
    asm volatile("cp.async.cg.shared.global [%0], [%1], 16;" :: "r"(dst), "l"(src));
}
#define CPA_COMMIT() asm volatile("cp.async.commit_group;" ::: "memory")
#define CPA_WAIT0()  asm volatile("cp.async.wait_group 0;" ::: "memory")

__device__ __forceinline__ uint32_t tf32hi(float x) {
    uint32_t h;
    asm("cvt.rna.tf32.f32 %0, %1;" : "=r"(h) : "f"(x));
    return h;
}
// MMA: D += A(tf32) * B(tf32), m16n8k8
#define MMA8(dd, aa, bb)                                                        \
    asm volatile(                                                               \
        "mma.sync.aligned.m16n8k8.row.col.f32.tf32.tf32.f32 "                   \
        "{%0,%1,%2,%3},{%4,%5,%6,%7},{%8,%9},{%0,%1,%2,%3};"                    \
        : "+f"(dd[0]), "+f"(dd[1]), "+f"(dd[2]), "+f"(dd[3])                    \
        : "r"(aa[0]), "r"(aa[1]), "r"(aa[2]), "r"(aa[3]), "r"(bb[0]), "r"(bb[1]))

// ---------------- weight prep: w [64][K] -> tf32 hi/lo transposed [K][64] ----------------
__global__ void k_wprep(const float* __restrict__ w, int sel, int K) {
    int i = blockIdx.x * 256 + threadIdx.x;
    if (i < K * 64) {
        int k = i >> 6, o = i & 63;
        float x = w[o * K + k];
        uint32_t h = tf32hi(x);
        float lo = x - __uint_as_float(h);
        g_wThi[sel][i] = h;
        g_wTlo[sel][i] = tf32hi(lo);
    }
}

// ---------------- transpose fe [B,C,F] -> g_xbuf [B,F,C] ----------------
__global__ void k_transpose(const float* __restrict__ fe, int C, int F) {
    __shared__ float sm[32][33];
    int b = blockIdx.z;
    int f0 = blockIdx.x * 32;
    int tx = threadIdx.x, ty = threadIdx.y;
#pragma unroll
    for (int r = 0; r < 4; r++) {
        int c = ty + r * 8;
        int f = f0 + tx;
        float v = 0.f;
        if (f < F && c < C) v = fe[((size_t)b * C + c) * F + f];
        sm[c][tx] = v;
    }
    __syncthreads();
#pragma unroll
    for (int r = 0; r < 4; r++) {
        int f = f0 + ty + r * 8;
        int c = tx;
        if (f < F && c < C) g_xbuf[((size_t)b * F + f) * C + c] = sm[c][ty + r * 8];
    }
}

// ---------------- fused gather + feature build + tf32 MMA GEMM ----------------
// Tile: 128 faces (M) x 64 out (N). 128 threads = 4 warps; warp w owns faces
// [w*32, w*32+32). K = 4*CIN in 16-row chunks (4 input channels each).
// G (A matrix) [16k][136 pad] tf32 hi/lo, W (B) [16k][72 pad] tf32 hi/lo,
// double-buffered; cp.async raw gather single-buffered.
template <int CIN>
__global__ __launch_bounds__(128, 3) void k_conv(const int* __restrict__ gidx,
                                                 int wsel,
                                                 const float* __restrict__ bias,
                                                 int F) {
    constexpr int NG = CIN / 4;                // 16-k chunks
    // smem byte offsets
    constexpr int OFF_GH = 0;                  // 2 x [16][136] u32 = 17408
    constexpr int OFF_GL = 17408;              // 2 x 8704
    constexpr int OFF_WH = 34816;              // 2 x [16][72] u32 = 9216
    constexpr int OFF_WL = 44032;              // 2 x 4608
    constexpr int OFF_RAW = 53248;             // [4 src][128 faces][16B] = 8192
    constexpr int OFF_SIDX = 61440;            // [128][3] int
    constexpr int OFF_BIAS = 62976;            // 64 f32

    extern __shared__ char smc[];
    uint32_t sb = s2u(smc);
    int* sidx = (int*)(smc + OFF_SIDX);
    float* bias_s = (float*)(smc + OFF_BIAS);

    int t = threadIdx.x;
    int warp = t >> 5, lane = t & 31;
    int r = lane >> 2, c = lane & 3;
    int b = blockIdx.y;
    int f0 = blockIdx.x * 128;
    int nv = F - f0; if (nv > 128) nv = 128;

    if (t < 64) bias_s[t] = __ldg(&bias[t]);
    for (int i = t; i < 128 * 3; i += 128) {
        int fi = i / 3, j = i - fi * 3;
        sidx[i] = (f0 + fi < F) ? __ldg(&gidx[((size_t)b * F + f0 + fi) * 3 + j]) : 0;
    }
    __syncthreads();

    // per-thread gather sources (thread t owns face t)
    int fc = f0 + (t < nv ? t : (nv - 1));
    const float* s0 = &g_xbuf[((size_t)b * F + fc) * CIN];
    const float* s1 = &g_xbuf[((size_t)b * F + sidx[t * 3 + 0]) * CIN];
    const float* s2 = &g_xbuf[((size_t)b * F + sidx[t * 3 + 1]) * CIN];
    const float* s3 = &g_xbuf[((size_t)b * F + sidx[t * 3 + 2]) * CIN];
    const uint32_t* wThi = g_wThi[wsel];
    const uint32_t* wTlo = g_wTlo[wsel];
    bool fv = t < nv;

    auto ISSUE = [&](int g) {
        int buf = g & 1;
        // raw gather: 4 sources x 16B (4 channels) per face
        uint32_t rb = sb + OFF_RAW + t * 16;
        cpa16(rb, s0 + g * 4);
        cpa16(rb + 2048, s1 + g * 4);
        cpa16(rb + 4096, s2 + g * 4);
        cpa16(rb + 6144, s3 + g * 4);
        // weights: 16 rows x 64, pad stride 72 (288B rows); 2 float4 per thread per split
#pragma unroll
        for (int j = 0; j < 2; j++) {
            int idx = j * 128 + t;
            int k = idx >> 4, oq = idx & 15;
            cpa16(sb + OFF_WH + buf * 4608 + k * 288 + oq * 16, wThi + g * 1024 + k * 64 + oq * 4);
            cpa16(sb + OFF_WL + buf * 4608 + k * 288 + oq * 16, wTlo + g * 1024 + k * 64 + oq * 4);
        }
        CPA_COMMIT();
    };

    auto CONVERT = [&](int g) {
        int buf = g & 1;
        const float4* rp = (const float4*)(smc + OFF_RAW);
        float4 vc = rp[t], v1 = rp[128 + t], v2 = rp[256 + t], v3 = rp[384 + t];
        uint32_t* Gh = (uint32_t*)(smc + OFF_GH + buf * 8704);
        uint32_t* Gl = (uint32_t*)(smc + OFF_GL + buf * 8704);
        const float* pc = (const float*)&vc;
        const float* p1 = (const float*)&v1;
        const float* p2 = (const float*)&v2;
        const float* p3 = (const float*)&v3;
#pragma unroll
        for (int cc = 0; cc < 4; cc++) {
            float x1 = p1[cc], x2 = p2[cc], x3 = p3[cc];
            float f[4];
            f[0] = fv ? pc[cc] : 0.f;
            f[1] = fv ? (x1 + x2 + x3) : 0.f;
            f[2] = fv ? (fabsf(x1 - x2) + fabsf(x2 - x3) + fabsf(x3 - x1)) : 0.f;
            f[3] = fv ? fmaxf(x1, fmaxf(x2, x3)) : 0.f;
#pragma unroll
            for (int ft = 0; ft < 4; ft++) {
                int k = cc * 4 + ft;
                uint32_t h = tf32hi(f[ft]);
                float lo = f[ft] - __uint_as_float(h);
                Gh[k * 136 + t] = h;
                Gl[k * 136 + t] = tf32hi(lo);
            }
        }
    };

    // accumulators: 2 m-tiles x 8 n-tiles x 4 regs
    float d[2][8][4];
#pragma unroll
    for (int m = 0; m < 2; m++)
#pragma unroll
        for (int n = 0; n < 8; n++)
#pragma unroll
            for (int q = 0; q < 4; q++) d[m][n][q] = 0.f;

    int m0 = warp * 32;

    auto GEMM = [&](int g) {
        int buf = g & 1;
        const uint32_t* Gh = (const uint32_t*)(smc + OFF_GH + buf * 8704);
        const uint32_t* Gl = (const uint32_t*)(smc + OFF_GL + buf * 8704);
        const uint32_t* Wh = (const uint32_t*)(smc + OFF_WH + buf * 4608);
        const uint32_t* Wl = (const uint32_t*)(smc + OFF_WL + buf * 4608);
#pragma unroll
        for (int ks = 0; ks < 2; ks++) {
            int kk = ks * 8;
            uint32_t ah[2][4], al[2][4];
#pragma unroll
            for (int m = 0; m < 2; m++) {
                int f = m0 + m * 16 + r;
                ah[m][0] = Gh[(kk + c) * 136 + f];
                ah[m][1] = Gh[(kk + c) * 136 + f + 8];
                ah[m][2] = Gh[(kk + c + 4) * 136 + f];
                ah[m][3] = Gh[(kk + c + 4) * 136 + f + 8];
                al[m][0] = Gl[(kk + c) * 136 + f];
                al[m][1] = Gl[(kk + c) * 136 + f + 8];
                al[m][2] = Gl[(kk + c + 4) * 136 + f];
                al[m][3] = Gl[(kk + c + 4) * 136 + f + 8];
            }
            uint32_t bh[8][2], bl[8][2];
#pragma unroll
            for (int n = 0; n < 8; n++) {
                int col = n * 8 + r;
                bh[n][0] = Wh[(kk + c) * 72 + col];
                bh[n][1] = Wh[(kk + c + 4) * 72 + col];
                bl[n][0] = Wl[(kk + c) * 72 + col];
                bl[n][1] = Wl[(kk + c + 4) * 72 + col];
            }
#pragma unroll
            for (int m = 0; m < 2; m++)
#pragma unroll
                for (int n = 0; n < 8; n++) {
                    MMA8(d[m][n], ah[m], bh[n]);
                    MMA8(d[m][n], ah[m], bl[n]);
                    MMA8(d[m][n], al[m], bh[n]);
                }
        }
    };

    // pipeline
    ISSUE(0);
    CPA_WAIT0();
    CONVERT(0);
    __syncthreads();
#pragma unroll 1
    for (int g = 0; g < NG; g++) {
        if (g + 1 < NG) ISSUE(g + 1);
        GEMM(g);
        if (g + 1 < NG) {
            CPA_WAIT0();
            CONVERT(g + 1);
            __syncthreads();
        }
    }
    __syncthreads();   // all warps done reading smem; reuse G area for reductions

    // epilogue: bias, store y [B,F,64], per-(warp,row) partial sums
    float ls[16], lq[16];
#pragma unroll
    for (int i = 0; i < 16; i++) { ls[i] = 0.f; lq[i] = 0.f; }
#pragma unroll
    for (int m = 0; m < 2; m++) {
        int fA = m0 + m * 16 + r;
        int fB = fA + 8;
#pragma unroll
        for (int n = 0; n < 8; n++) {
            int c0 = n * 8 + 2 * c;
            float b0 = bias_s[c0], b1 = bias_s[c0 + 1];
            float v00 = d[m][n][0] + b0, v01 = d[m][n][1] + b1;
            float v10 = d[m][n][2] + b0, v11 = d[m][n][3] + b1;
            if (fA < nv) {
                *(float2*)&g_ybuf[((size_t)b * F + f0 + fA) * 64 + c0] = make_float2(v00, v01);
                ls[n * 2] += v00; lq[n * 2] += v00 * v00;
                ls[n * 2 + 1] += v01; lq[n * 2 + 1] += v01 * v01;
            }
            if (fB < nv) {
                *(float2*)&g_ybuf[((size_t)b * F + f0 + fB) * 64 + c0] = make_float2(v10, v11);
                ls[n * 2] += v10; lq[n * 2] += v10 * v10;
                ls[n * 2 + 1] += v11; lq[n * 2 + 1] += v11 * v11;
            }
        }
    }
    // reduction: redS[32 rows][64]; row = warp*8 + r, 4 lanes (c) cover 64 channels
    float* redS = (float*)(smc);            // 8KB
    float* redQ = (float*)(smc + 8192);     // 8KB
    int row = warp * 8 + r;
#pragma unroll
    for (int n = 0; n < 8; n++) {
        redS[row * 64 + n * 8 + 2 * c] = ls[n * 2];
        redS[row * 64 + n * 8 + 2 * c + 1] = ls[n * 2 + 1];
        redQ[row * 64 + n * 8 + 2 * c] = lq[n * 2];
        redQ[row * 64 + n * 8 + 2 * c + 1] = lq[n * 2 + 1];
    }
    __syncthreads();
    if (t < 64) {
        float s = 0.f, q = 0.f;
#pragma unroll 8
        for (int i = 0; i < 32; i++) { s += redS[i * 64 + t]; q += redQ[i * 64 + t]; }
        int bid = blockIdx.y * gridDim.x + blockIdx.x;
        g_psum[bid * 64 + t] = s;
        g_psumsq[bid * 64 + t] = q;
    }
}

// ---------------- BN stats finalize ----------------
__global__ void k_stats(const float* __restrict__ gamma,
                        const float* __restrict__ beta, int stage, int nblk,
                        float invN) {
    __shared__ float smS[4][64], smQ[4][64];
    int t = threadIdx.x;
    int c = t & 63, sl = t >> 6;
    float s = 0.f, q = 0.f;
    for (int i = sl; i < nblk; i += 4) {
        s += g_psum[i * 64 + c];
        q += g_psumsq[i * 64 + c];
    }
    smS[sl][c] = s; smQ[sl][c] = q;
    __syncthreads();
    if (t < 64) {
        float ss = smS[0][t] + smS[1][t] + smS[2][t] + smS[3][t];
        float qq = smQ[0][t] + smQ[1][t] + smQ[2][t] + smQ[3][t];
        float m = ss * invN;
        float var = qq * invN - m * m;
        float rstd = rsqrtf(var + 1e-5f);
        float a = gamma[t] * rstd;
        g_coefA[stage * 64 + t] = a;
        g_coefS[stage * 64 + t] = beta[t] - m * a;
    }
}

// ---------------- apply BN + (residual) + lrelu -> g_xbuf [B,F,64] ----------------
__global__ void k_apply(int stage, int res, int nvec) {
    int i = blockIdx.x * blockDim.x + threadIdx.x;
    if (i >= nvec) return;
    int c4 = i & 15;
    float4 a = *(const float4*)&g_coefA[stage * 64 + c4 * 4];
    float4 s = *(const float4*)&g_coefS[stage * 64 + c4 * 4];
    float4 yv = ((const float4*)g_ybuf)[i];
    float4 o;
    o.x = a.x * yv.x + s.x; o.y = a.y * yv.y + s.y;
    o.z = a.z * yv.z + s.z; o.w = a.w * yv.w + s.w;
    if (res) {
        float4 xv = ((const float4*)g_xbuf)[i];
        o.x += xv.x; o.y += xv.y; o.z += xv.z; o.w += xv.w;
    }
    o.x = lrelu(o.x); o.y = lrelu(o.y); o.z = lrelu(o.z); o.w = lrelu(o.w);
    ((float4*)g_xbuf)[i] = o;
}

// ---------------- final apply + transpose to [B,O,F] ----------------
__global__ void k_apply_out(float* __restrict__ out, int F) {
    __shared__ float sm[32][33];
    int b = blockIdx.z;
    int o0 = blockIdx.y * 32;
    int f0 = blockIdx.x * 32;
    int tx = threadIdx.x, ty = threadIdx.y;
#pragma unroll
    for (int r = 0; r < 4; r++) {
        int f = f0 + ty + r * 8;
        int o = o0 + tx;
        float v = 0.f;
        if (f < F) {
            float a = g_coefA[2 * 64 + o], s = g_coefS[2 * 64 + o];
            size_t idx = ((size_t)b * F + f) * 64 + o;
            v = lrelu(a * g_ybuf[idx] + s + g_xbuf[idx]);
        }
        sm[ty + r * 8][tx] = v;
    }
    __syncthreads();
#pragma unroll
    for (int r = 0; r < 4; r++) {
        int o = o0 + ty + r * 8;
        int f = f0 + tx;
        if (f < F) out[((size_t)b * 64 + o) * F + f] = sm[tx][ty + r * 8];
    }
}

// ---------------- host launcher ----------------
extern "C" void kernel_launch(void* const* d_in, const int* in_sizes, int n_in,
                              void* d_out, int out_size) {
    const float* fe  = (const float*)d_in[0];
    const int*   gm  = (const int*)d_in[1];
    const float* w1  = (const float*)d_in[2];
    const float* b1  = (const float*)d_in[3];
    const float* w2a = (const float*)d_in[4];
    const float* b2a = (const float*)d_in[5];
    const float* w2b = (const float*)d_in[6];
    const float* b2b = (const float*)d_in[7];
    const float* g0  = (const float*)d_in[8];
    const float* be0 = (const float*)d_in[9];
    const float* g1  = (const float*)d_in[10];
    const float* be1 = (const float*)d_in[11];
    const float* g2  = (const float*)d_in[12];
    const float* be2 = (const float*)d_in[13];

    const int B = 4;
    const int F = in_sizes[1] / (3 * B);      // 50000
    const int Cin = in_sizes[0] / (B * F);    // 32

    const int SH = 63232;
    cudaFuncSetAttribute(k_conv<32>, cudaFuncAttributeMaxDynamicSharedMemorySize, SH);
    cudaFuncSetAttribute(k_conv<64>, cudaFuncAttributeMaxDynamicSharedMemorySize, SH);

    dim3 tb(32, 8);
    int ftiles32 = (F + 31) / 32;
    int fb = (F + 127) / 128;
    int nblk = fb * B;
    float invN = 1.0f / (float)(B * F);
    int nvec = B * F * 16;

    // prep
    k_wprep<<<(4 * Cin * 64 + 255) / 256, 256>>>(w1, 0, 4 * Cin);
    k_wprep<<<(256 * 64 + 255) / 256, 256>>>(w2a, 1, 256);
    k_wprep<<<(256 * 64 + 255) / 256, 256>>>(w2b, 2, 256);
    k_transpose<<<dim3(ftiles32, 1, B), tb>>>(fe, Cin, F);

    // stage 0
    k_conv<32><<<dim3(fb, B), 128, SH>>>(gm, 0, b1, F);
    k_stats<<<1, 256>>>(g0, be0, 0, nblk, invN);
    k_apply<<<(nvec + 255) / 256, 256>>>(0, 0, nvec);

    // stage 1 (residual)
    k_conv<64><<<dim3(fb, B), 128, SH>>>(gm, 1, b2a, F);
    k_stats<<<1, 256>>>(g1, be1, 1, nblk, invN);
    k_apply<<<(nvec + 255) / 256, 256>>>(1, 1, nvec);

    // stage 2 (residual, fused final transpose)
    k_conv<64><<<dim3(fb, B), 128, SH>>>(gm, 2, b2b, F);
    k_stats<<<1, 256>>>(g2, be2, 2, nblk, invN);
    k_apply_out<<<dim3(ftiles32, 2, B), tb>>>((float*)d_out, F);
}